// round 7
// baseline (speedup 1.0000x reference)
#include <cuda_runtime.h>

// E3nnSimpleNodeBlock: out = TensorSquare(feats+msgs), N=131072, MUL=16.
// Round 5: R2's register discipline (rolled v-loop, px0 via volatile SMEM,
// launch_bounds(128,3) -> 168-reg cap) + R3/R4's weight path (per-w SMEM slab,
// double-buffered cp.async, broadcast LDS.128). px1 register-resident.

#define T 128
#define NODES_PER_BLOCK 256
#define NNODES 131072

typedef unsigned long long u64;

// Splatted, pre-scaled weights. Layout: [w][v][32 ulonglong2]; each ulonglong2 holds
// two consecutive splatted weights, slot order [000 u0..15 | 110 | 101 | 112]. 128 KB.
__device__ ulonglong2 PW2[16 * 16 * 32];

// ---------- f32x2 helpers ----------
__device__ __forceinline__ u64 f2fma(u64 a, u64 b, u64 c) {
    u64 d;
    asm("fma.rn.f32x2 %0, %1, %2, %3;" : "=l"(d) : "l"(a), "l"(b), "l"(c));
    return d;
}
__device__ __forceinline__ u64 f2add(u64 a, u64 b) {
    u64 d;
    asm("add.rn.f32x2 %0, %1, %2;" : "=l"(d) : "l"(a), "l"(b));
    return d;
}
__device__ __forceinline__ u64 f2mul(u64 a, u64 b) {
    u64 d;
    asm("mul.rn.f32x2 %0, %1, %2;" : "=l"(d) : "l"(a), "l"(b));
    return d;
}
__device__ __forceinline__ u64 fpack(float lo, float hi) {
    u64 d;
    asm("mov.b64 %0, {%1, %2};" : "=l"(d) : "f"(lo), "f"(hi));
    return d;
}
__device__ __forceinline__ void funpack(u64 p, float& lo, float& hi) {
    asm("mov.b64 {%0, %1}, %2;" : "=f"(lo), "=f"(hi) : "l"(p));
}

// ---------- weight prep: transpose + scale + splat, [w][v][slot] ----------
__global__ void prep_kernel(const float* __restrict__ w000, const float* __restrict__ w101,
                            const float* __restrict__ w110, const float* __restrict__ w112) {
    int idx = blockIdx.x * blockDim.x + threadIdx.x;   // 0 .. 16383
    if (idx >= 16 * 16 * 64) return;
    int w = idx >> 10;
    int v = (idx >> 6) & 15;
    int slot = idx & 63;
    int which = slot >> 4, u = slot & 15;
    int widx = u * 256 + v * 16 + w;                   // w[u][v][w], row-major
    const float A000 = 0.04419417382415922f;           // sqrt(1/(2*MUL*MUL))
    const float A110 = 0.02551551815399144f;           // A000/sqrt(3)
    const float A101 = 0.0625f;                        // sqrt(3/MUL^2)/sqrt(3)
    const float A112 = 0.13975424859373686f;           // sqrt(5)/16
    float val;
    if (which == 0)      val = A000 * w000[widx];
    else if (which == 1) val = A110 * w110[widx];
    else if (which == 2) val = A101 * w101[widx];
    else                 val = A112 * w112[widx];
    reinterpret_cast<float2*>(PW2)[idx] = make_float2(val, val);   // splat
}

// ---------- main kernel ----------
__global__ __launch_bounds__(T, 3) void e3nn_kernel(const float* __restrict__ feats,
                                                    const float* __restrict__ msgs,
                                                    float* __restrict__ out) {
    // Dynamic SMEM layout (per CTA, 80 KB):
    //   wbuf : ulonglong2[2][512]  (16 KB)  per-w weight slab, double-buffered
    //   xs0u : u64[16*T]           (16 KB)  {x0[v]} pairs (stage-1 u reads + stage-2 v reads)
    //   xsA  : ulonglong2[16*T]    (32 KB)  {x1[v][0], x1[v][1]}
    //   xsB  : u64[16*T]           (16 KB)  {x1[v][2]}
    extern __shared__ u64 sm[];
    ulonglong2* wbuf = reinterpret_cast<ulonglong2*>(sm);            // 2*512 ull2
    u64* xs0u = sm + 2048;                                           // 16*T u64
    ulonglong2* xsA = reinterpret_cast<ulonglong2*>(sm + 2048 + 16 * T);
    u64* xsB = sm + 2048 + 16 * T + 32 * T;

    const int t = threadIdx.x;
    const int nA = blockIdx.x * NODES_PER_BLOCK + t;
    const int nB = nA + T;

    // ---- load x = feats + msgs for both nodes, pack into f32x2 ----
    u64 px1[16][3];   // register-resident for stage-1
    {
        float xA[64], xB[64];
        const float4* fA = reinterpret_cast<const float4*>(feats) + nA * 16;
        const float4* mA = reinterpret_cast<const float4*>(msgs) + nA * 16;
        const float4* fB = reinterpret_cast<const float4*>(feats) + nB * 16;
        const float4* mB = reinterpret_cast<const float4*>(msgs) + nB * 16;
#pragma unroll
        for (int q = 0; q < 16; ++q) {
            float4 f = fA[q], m = mA[q];
            xA[4 * q + 0] = f.x + m.x; xA[4 * q + 1] = f.y + m.y;
            xA[4 * q + 2] = f.z + m.z; xA[4 * q + 3] = f.w + m.w;
        }
#pragma unroll
        for (int q = 0; q < 16; ++q) {
            float4 f = fB[q], m = mB[q];
            xB[4 * q + 0] = f.x + m.x; xB[4 * q + 1] = f.y + m.y;
            xB[4 * q + 2] = f.z + m.z; xB[4 * q + 3] = f.w + m.w;
        }
        // x0 pairs live ONLY in SMEM (kept out of the register file)
#pragma unroll
        for (int v = 0; v < 16; ++v) xs0u[v * T + t] = fpack(xA[v], xB[v]);
#pragma unroll
        for (int v = 0; v < 16; ++v) {
#pragma unroll
            for (int i = 0; i < 3; ++i) px1[v][i] = fpack(xA[16 + 3 * v + i], xB[16 + 3 * v + i]);
        }
    }
    // stage-2 operand stash (thread-private slots; no sync needed)
#pragma unroll
    for (int v = 0; v < 16; ++v) {
        xsA[v * T + t] = make_ulonglong2(px1[v][0], px1[v][1]);
        xsB[v * T + t] = px1[v][2];
    }

    // ---- cp.async weight staging (4 x 16B per thread = 8 KB per slab) ----
    const ulonglong2* gw = PW2;
#define STAGE_SLAB(wi, buf)                                                              \
    do {                                                                                 \
        unsigned saddr = (unsigned)__cvta_generic_to_shared(&wbuf[(buf) * 512 + t * 4]); \
        const ulonglong2* src = gw + (wi) * 512 + t * 4;                                 \
        asm volatile("cp.async.cg.shared.global [%0], [%1], 16;" ::"r"(saddr), "l"(src));          \
        asm volatile("cp.async.cg.shared.global [%0], [%1], 16;" ::"r"(saddr + 16), "l"(src + 1)); \
        asm volatile("cp.async.cg.shared.global [%0], [%1], 16;" ::"r"(saddr + 32), "l"(src + 2)); \
        asm volatile("cp.async.cg.shared.global [%0], [%1], 16;" ::"r"(saddr + 48), "l"(src + 3)); \
        asm volatile("cp.async.commit_group;");                                          \
    } while (0)

    STAGE_SLAB(0, 0);
    asm volatile("cp.async.wait_group 0;");
    __syncthreads();

    float* outA = out + (long)nA * 144;
    float* outB = out + (long)nB * 144;

#pragma unroll 1
    for (int w = 0; w < 16; ++w) {
        // prefetch next slab into the other buffer (safe: everyone synced after w-1)
        if (w < 15) STAGE_SLAB(w + 1, (w + 1) & 1);

        const ulonglong2* __restrict__ cw = wbuf + (w & 1) * 512;

        u64 acc00 = 0, acc01 = 0;              // out0 paths (000 / 110)
        u64 a10 = 0, a11 = 0, a12 = 0;         // out1 k=0..2
        u64 P0 = 0, P1 = 0, P2 = 0;            // out2 diagonal sums
        u64 Q01 = 0, Q02 = 0, Q12 = 0;         // out2 cross sums

#pragma unroll 1
        for (int v = 0; v < 16; ++v) {
            const ulonglong2* __restrict__ pwv = cw + v * 32;   // uniform (broadcast) LDS

            u64 s000 = 0;
            u64 s110_0 = 0, s110_1 = 0, s110_2 = 0;
            u64 s101_0 = 0, s101_1 = 0, s101_2 = 0;
            u64 s112_0 = 0, s112_1 = 0, s112_2 = 0;

#pragma unroll
            for (int g = 0; g < 8; ++g) {                 // w000 (x0 via volatile SMEM: no hoist)
                ulonglong2 q = pwv[g];
                u64 x0a = *(volatile const u64*)&xs0u[(2 * g + 0) * T + t];
                u64 x0b = *(volatile const u64*)&xs0u[(2 * g + 1) * T + t];
                s000 = f2fma(q.x, x0a, s000);
                s000 = f2fma(q.y, x0b, s000);
            }
#pragma unroll
            for (int g = 0; g < 8; ++g) {                 // w110
                ulonglong2 q = pwv[8 + g];
                s110_0 = f2fma(q.x, px1[2 * g][0], s110_0);
                s110_1 = f2fma(q.x, px1[2 * g][1], s110_1);
                s110_2 = f2fma(q.x, px1[2 * g][2], s110_2);
                s110_0 = f2fma(q.y, px1[2 * g + 1][0], s110_0);
                s110_1 = f2fma(q.y, px1[2 * g + 1][1], s110_1);
                s110_2 = f2fma(q.y, px1[2 * g + 1][2], s110_2);
            }
#pragma unroll
            for (int g = 0; g < 8; ++g) {                 // w101
                ulonglong2 q = pwv[16 + g];
                s101_0 = f2fma(q.x, px1[2 * g][0], s101_0);
                s101_1 = f2fma(q.x, px1[2 * g][1], s101_1);
                s101_2 = f2fma(q.x, px1[2 * g][2], s101_2);
                s101_0 = f2fma(q.y, px1[2 * g + 1][0], s101_0);
                s101_1 = f2fma(q.y, px1[2 * g + 1][1], s101_1);
                s101_2 = f2fma(q.y, px1[2 * g + 1][2], s101_2);
            }
#pragma unroll
            for (int g = 0; g < 8; ++g) {                 // w112
                ulonglong2 q = pwv[24 + g];
                s112_0 = f2fma(q.x, px1[2 * g][0], s112_0);
                s112_1 = f2fma(q.x, px1[2 * g][1], s112_1);
                s112_2 = f2fma(q.x, px1[2 * g][2], s112_2);
                s112_0 = f2fma(q.y, px1[2 * g + 1][0], s112_0);
                s112_1 = f2fma(q.y, px1[2 * g + 1][1], s112_1);
                s112_2 = f2fma(q.y, px1[2 * g + 1][2], s112_2);
            }

            // stage-2 operands for dynamic v (SMEM stash, conflict-free strides)
            u64 x0v = xs0u[v * T + t];
            ulonglong2 xa = xsA[v * T + t];   // {x1[v][0], x1[v][1]}
            u64 x1v2 = xsB[v * T + t];

            acc00 = f2fma(s000, x0v, acc00);
            acc01 = f2fma(s110_0, xa.x, acc01);
            acc01 = f2fma(s110_1, xa.y, acc01);
            acc01 = f2fma(s110_2, x1v2, acc01);

            a10 = f2fma(s101_0, x0v, a10);
            a11 = f2fma(s101_1, x0v, a11);
            a12 = f2fma(s101_2, x0v, a12);

            P0 = f2fma(s112_0, xa.x, P0);
            P1 = f2fma(s112_1, xa.y, P1);
            P2 = f2fma(s112_2, x1v2, P2);
            Q01 = f2fma(s112_0, xa.y, Q01);
            Q01 = f2fma(s112_1, xa.x, Q01);
            Q02 = f2fma(s112_0, x1v2, Q02);
            Q02 = f2fma(s112_2, xa.x, Q02);
            Q12 = f2fma(s112_1, x1v2, Q12);
            Q12 = f2fma(s112_2, xa.y, Q12);
        }

        // ---- epilogue for this w ----
        const u64 CS2  = fpack(0.31622776601683794f, 0.31622776601683794f); // 1/sqrt(10)
        const u64 C62  = fpack(0.18257418583505536f, 0.18257418583505536f); // 1/sqrt(30)
        const u64 NEG1 = fpack(-1.0f, -1.0f);
        const u64 TWO2 = fpack(2.0f, 2.0f);

        float a, b;
        funpack(f2add(acc00, acc01), a, b);
        outA[w] = a; outB[w] = b;

        funpack(a10, a, b); outA[16 + 3 * w + 0] = a; outB[16 + 3 * w + 0] = b;
        funpack(a11, a, b); outA[16 + 3 * w + 1] = a; outB[16 + 3 * w + 1] = b;
        funpack(a12, a, b); outA[16 + 3 * w + 2] = a; outB[16 + 3 * w + 2] = b;

        funpack(f2mul(CS2, Q01), a, b); outA[64 + 5 * w + 0] = a; outB[64 + 5 * w + 0] = b;
        funpack(f2mul(CS2, Q02), a, b); outA[64 + 5 * w + 1] = a; outB[64 + 5 * w + 1] = b;
        funpack(f2mul(CS2, Q12), a, b); outA[64 + 5 * w + 2] = a; outB[64 + 5 * w + 2] = b;

        u64 d3 = f2fma(P1, NEG1, P0);                 // P0 - P1
        funpack(f2mul(CS2, d3), a, b); outA[64 + 5 * w + 3] = a; outB[64 + 5 * w + 3] = b;

        u64 s01 = f2add(P0, P1);
        u64 d4 = f2fma(TWO2, P2, f2mul(s01, NEG1));   // 2*P2 - P0 - P1
        funpack(f2mul(C62, d4), a, b); outA[64 + 5 * w + 4] = a; outB[64 + 5 * w + 4] = b;

        // next slab staged; make it visible before next iteration reads it
        asm volatile("cp.async.wait_group 0;");
        __syncthreads();
    }
#undef STAGE_SLAB
}

extern "C" void kernel_launch(void* const* d_in, const int* in_sizes, int n_in,
                              void* d_out, int out_size) {
    const float* feats = (const float*)d_in[0];
    const float* msgs  = (const float*)d_in[1];
    const float* w000  = (const float*)d_in[2];
    const float* w101  = (const float*)d_in[3];
    const float* w110  = (const float*)d_in[4];
    const float* w112  = (const float*)d_in[5];
    float* out = (float*)d_out;

    const int smem_bytes = (2048 + 64 * T) * (int)sizeof(u64);   // 16 KB + 64 KB = 80 KB
    cudaFuncSetAttribute(e3nn_kernel, cudaFuncAttributeMaxDynamicSharedMemorySize, smem_bytes);

    prep_kernel<<<64, 256>>>(w000, w101, w110, w112);
    e3nn_kernel<<<NNODES / NODES_PER_BLOCK, T, smem_bytes>>>(feats, msgs, out);
}

// round 8
// speedup vs baseline: 1.3119x; 1.3119x over previous
#include <cuda_runtime.h>

// E3nnSimpleNodeBlock: out = TensorSquare(feats+msgs), N=131072, MUL=16.
// Round 7: R4 compute config (px0+px1 in regs, rolled v-loop, SMEM stash for
// stage-2 dynamic-v operands, per-w SMEM weight slab) + coalesced output path:
// outputs staged in SMEM per 4-w group, flushed as float4 (contiguous runs
// per node: out0 1xf4, out1 3xf4, out2 5xf4) -> ~10x fewer store wavefronts.

#define T 128
#define NODES_PER_BLOCK 256
#define NNODES 131072

typedef unsigned long long u64;

// Splatted, pre-scaled weights. Layout: [w][v][32 ulonglong2]; each ulonglong2 holds
// two consecutive splatted weights, slot order [000 u0..15 | 110 | 101 | 112]. 128 KB.
__device__ ulonglong2 PW2[16 * 16 * 32];

// ---------- f32x2 helpers ----------
__device__ __forceinline__ u64 f2fma(u64 a, u64 b, u64 c) {
    u64 d;
    asm("fma.rn.f32x2 %0, %1, %2, %3;" : "=l"(d) : "l"(a), "l"(b), "l"(c));
    return d;
}
__device__ __forceinline__ u64 f2add(u64 a, u64 b) {
    u64 d;
    asm("add.rn.f32x2 %0, %1, %2;" : "=l"(d) : "l"(a), "l"(b));
    return d;
}
__device__ __forceinline__ u64 f2mul(u64 a, u64 b) {
    u64 d;
    asm("mul.rn.f32x2 %0, %1, %2;" : "=l"(d) : "l"(a), "l"(b));
    return d;
}
__device__ __forceinline__ u64 fpack(float lo, float hi) {
    u64 d;
    asm("mov.b64 %0, {%1, %2};" : "=l"(d) : "f"(lo), "f"(hi));
    return d;
}
__device__ __forceinline__ void funpack(u64 p, float& lo, float& hi) {
    asm("mov.b64 {%0, %1}, %2;" : "=f"(lo), "=f"(hi) : "l"(p));
}

// ---------- weight prep: transpose + scale + splat, [w][v][slot] ----------
__global__ void prep_kernel(const float* __restrict__ w000, const float* __restrict__ w101,
                            const float* __restrict__ w110, const float* __restrict__ w112) {
    int idx = blockIdx.x * blockDim.x + threadIdx.x;   // 0 .. 16383
    if (idx >= 16 * 16 * 64) return;
    int w = idx >> 10;
    int v = (idx >> 6) & 15;
    int slot = idx & 63;
    int which = slot >> 4, u = slot & 15;
    int widx = u * 256 + v * 16 + w;                   // w[u][v][w], row-major
    const float A000 = 0.04419417382415922f;           // sqrt(1/(2*MUL*MUL))
    const float A110 = 0.02551551815399144f;           // A000/sqrt(3)
    const float A101 = 0.0625f;                        // sqrt(3/MUL^2)/sqrt(3)
    const float A112 = 0.13975424859373686f;           // sqrt(5)/16
    float val;
    if (which == 0)      val = A000 * w000[widx];
    else if (which == 1) val = A110 * w110[widx];
    else if (which == 2) val = A101 * w101[widx];
    else                 val = A112 * w112[widx];
    reinterpret_cast<float2*>(PW2)[idx] = make_float2(val, val);   // splat
}

// ---------- main kernel ----------
__global__ __launch_bounds__(T, 2) void e3nn_kernel(const float* __restrict__ feats,
                                                    const float* __restrict__ msgs,
                                                    float* __restrict__ out) {
    // Dynamic SMEM layout (per CTA, 108 KB):
    //   wbuf  : ulonglong2[512]   (8 KB)   per-w weight slab (single-buffered)
    //   xs0u  : u64[16*T]         (16 KB)  {x0[v]} pairs (stage-2 dynamic-v reads)
    //   xsA   : ulonglong2[16*T]  (32 KB)  {x1[v][0], x1[v][1]}
    //   xsB   : u64[16*T]         (16 KB)  {x1[v][2]}
    //   stage : float[256*36]     (36 KB)  4-w-group output staging (9 float4 / node)
    extern __shared__ u64 sm[];
    ulonglong2* wbuf = reinterpret_cast<ulonglong2*>(sm);            // 512 ull2
    u64* xs0u = sm + 1024;                                           // 16*T u64
    ulonglong2* xsA = reinterpret_cast<ulonglong2*>(sm + 1024 + 16 * T);
    u64* xsB = sm + 1024 + 16 * T + 32 * T;
    float* stage = reinterpret_cast<float*>(sm + 1024 + 64 * T);     // 9216 floats

    const int t = threadIdx.x;
    const int nA = blockIdx.x * NODES_PER_BLOCK + t;
    const int nB = nA + T;

    // ---- load x = feats + msgs for both nodes, pack into f32x2 registers ----
    u64 px0[16];
    u64 px1[16][3];
    {
        float xA[64], xB[64];
        const float4* fA = reinterpret_cast<const float4*>(feats) + nA * 16;
        const float4* mA = reinterpret_cast<const float4*>(msgs) + nA * 16;
        const float4* fB = reinterpret_cast<const float4*>(feats) + nB * 16;
        const float4* mB = reinterpret_cast<const float4*>(msgs) + nB * 16;
#pragma unroll
        for (int q = 0; q < 16; ++q) {
            float4 f = fA[q], m = mA[q];
            xA[4 * q + 0] = f.x + m.x; xA[4 * q + 1] = f.y + m.y;
            xA[4 * q + 2] = f.z + m.z; xA[4 * q + 3] = f.w + m.w;
        }
#pragma unroll
        for (int q = 0; q < 16; ++q) {
            float4 f = fB[q], m = mB[q];
            xB[4 * q + 0] = f.x + m.x; xB[4 * q + 1] = f.y + m.y;
            xB[4 * q + 2] = f.z + m.z; xB[4 * q + 3] = f.w + m.w;
        }
#pragma unroll
        for (int v = 0; v < 16; ++v) px0[v] = fpack(xA[v], xB[v]);
#pragma unroll
        for (int v = 0; v < 16; ++v) {
#pragma unroll
            for (int i = 0; i < 3; ++i) px1[v][i] = fpack(xA[16 + 3 * v + i], xB[16 + 3 * v + i]);
        }
    }

    // ---- stage-2 operand stash (thread-private slots) ----
#pragma unroll
    for (int v = 0; v < 16; ++v) {
        xs0u[v * T + t] = px0[v];
        xsA[v * T + t] = make_ulonglong2(px1[v][0], px1[v][1]);
        xsB[v * T + t] = px1[v][2];
    }

    // ---- cp.async weight staging (4 x 16B per thread = 8 KB slab) ----
    const ulonglong2* gw = PW2;
#define STAGE_SLAB(wi)                                                                   \
    do {                                                                                 \
        unsigned saddr = (unsigned)__cvta_generic_to_shared(&wbuf[t * 4]);               \
        const ulonglong2* src = gw + (wi) * 512 + t * 4;                                 \
        asm volatile("cp.async.cg.shared.global [%0], [%1], 16;" ::"r"(saddr), "l"(src));          \
        asm volatile("cp.async.cg.shared.global [%0], [%1], 16;" ::"r"(saddr + 16), "l"(src + 1)); \
        asm volatile("cp.async.cg.shared.global [%0], [%1], 16;" ::"r"(saddr + 32), "l"(src + 2)); \
        asm volatile("cp.async.cg.shared.global [%0], [%1], 16;" ::"r"(saddr + 48), "l"(src + 3)); \
        asm volatile("cp.async.commit_group;");                                          \
    } while (0)

    const u64 CS2  = fpack(0.31622776601683794f, 0.31622776601683794f); // 1/sqrt(10)
    const u64 C62  = fpack(0.18257418583505536f, 0.18257418583505536f); // 1/sqrt(30)
    const u64 NEG1 = fpack(-1.0f, -1.0f);
    const u64 TWO2 = fpack(2.0f, 2.0f);

#pragma unroll 1
    for (int w = 0; w < 16; ++w) {
        // prior iter's wbuf reads + flush stage-reads complete before overwrite
        __syncthreads();
        STAGE_SLAB(w);
        asm volatile("cp.async.wait_group 0;");
        __syncthreads();

        const ulonglong2* __restrict__ cw = wbuf;

        u64 acc00 = 0, acc01 = 0;              // out0 paths (000 / 110)
        u64 a10 = 0, a11 = 0, a12 = 0;         // out1 k=0..2
        u64 P0 = 0, P1 = 0, P2 = 0;            // out2 diagonal sums
        u64 Q01 = 0, Q02 = 0, Q12 = 0;         // out2 cross sums

#pragma unroll 1
        for (int v = 0; v < 16; ++v) {
            const ulonglong2* __restrict__ pwv = cw + v * 32;   // uniform (broadcast) LDS

            u64 s000 = 0;
            u64 s110_0 = 0, s110_1 = 0, s110_2 = 0;
            u64 s101_0 = 0, s101_1 = 0, s101_2 = 0;
            u64 s112_0 = 0, s112_1 = 0, s112_2 = 0;

#pragma unroll
            for (int g = 0; g < 8; ++g) {                 // w000
                ulonglong2 q = pwv[g];
                s000 = f2fma(q.x, px0[2 * g + 0], s000);
                s000 = f2fma(q.y, px0[2 * g + 1], s000);
            }
#pragma unroll
            for (int g = 0; g < 8; ++g) {                 // w110
                ulonglong2 q = pwv[8 + g];
                s110_0 = f2fma(q.x, px1[2 * g][0], s110_0);
                s110_1 = f2fma(q.x, px1[2 * g][1], s110_1);
                s110_2 = f2fma(q.x, px1[2 * g][2], s110_2);
                s110_0 = f2fma(q.y, px1[2 * g + 1][0], s110_0);
                s110_1 = f2fma(q.y, px1[2 * g + 1][1], s110_1);
                s110_2 = f2fma(q.y, px1[2 * g + 1][2], s110_2);
            }
#pragma unroll
            for (int g = 0; g < 8; ++g) {                 // w101
                ulonglong2 q = pwv[16 + g];
                s101_0 = f2fma(q.x, px1[2 * g][0], s101_0);
                s101_1 = f2fma(q.x, px1[2 * g][1], s101_1);
                s101_2 = f2fma(q.x, px1[2 * g][2], s101_2);
                s101_0 = f2fma(q.y, px1[2 * g + 1][0], s101_0);
                s101_1 = f2fma(q.y, px1[2 * g + 1][1], s101_1);
                s101_2 = f2fma(q.y, px1[2 * g + 1][2], s101_2);
            }
#pragma unroll
            for (int g = 0; g < 8; ++g) {                 // w112
                ulonglong2 q = pwv[24 + g];
                s112_0 = f2fma(q.x, px1[2 * g][0], s112_0);
                s112_1 = f2fma(q.x, px1[2 * g][1], s112_1);
                s112_2 = f2fma(q.x, px1[2 * g][2], s112_2);
                s112_0 = f2fma(q.y, px1[2 * g + 1][0], s112_0);
                s112_1 = f2fma(q.y, px1[2 * g + 1][1], s112_1);
                s112_2 = f2fma(q.y, px1[2 * g + 1][2], s112_2);
            }

            // stage-2 operands for dynamic v (SMEM stash, conflict-free strides)
            u64 x0v = xs0u[v * T + t];
            ulonglong2 xa = xsA[v * T + t];   // {x1[v][0], x1[v][1]}
            u64 x1v2 = xsB[v * T + t];

            acc00 = f2fma(s000, x0v, acc00);
            acc01 = f2fma(s110_0, xa.x, acc01);
            acc01 = f2fma(s110_1, xa.y, acc01);
            acc01 = f2fma(s110_2, x1v2, acc01);

            a10 = f2fma(s101_0, x0v, a10);
            a11 = f2fma(s101_1, x0v, a11);
            a12 = f2fma(s101_2, x0v, a12);

            P0 = f2fma(s112_0, xa.x, P0);
            P1 = f2fma(s112_1, xa.y, P1);
            P2 = f2fma(s112_2, x1v2, P2);
            Q01 = f2fma(s112_0, xa.y, Q01);
            Q01 = f2fma(s112_1, xa.x, Q01);
            Q02 = f2fma(s112_0, x1v2, Q02);
            Q02 = f2fma(s112_2, xa.x, Q02);
            Q12 = f2fma(s112_1, x1v2, Q12);
            Q12 = f2fma(s112_2, xa.y, Q12);
        }

        // ---- stage this w's 9 outputs per node into SMEM (group of 4 w's) ----
        {
            const int w2 = w & 3;
            float* sA = stage + t * 36;
            float* sB = stage + (t + T) * 36;
            float a, b;
            funpack(f2add(acc00, acc01), a, b);
            sA[w2] = a; sB[w2] = b;                                   // out0, rel col w2

            funpack(a10, a, b); sA[4 + 3 * w2 + 0] = a; sB[4 + 3 * w2 + 0] = b;
            funpack(a11, a, b); sA[4 + 3 * w2 + 1] = a; sB[4 + 3 * w2 + 1] = b;
            funpack(a12, a, b); sA[4 + 3 * w2 + 2] = a; sB[4 + 3 * w2 + 2] = b;

            funpack(f2mul(CS2, Q01), a, b); sA[16 + 5 * w2 + 0] = a; sB[16 + 5 * w2 + 0] = b;
            funpack(f2mul(CS2, Q02), a, b); sA[16 + 5 * w2 + 1] = a; sB[16 + 5 * w2 + 1] = b;
            funpack(f2mul(CS2, Q12), a, b); sA[16 + 5 * w2 + 2] = a; sB[16 + 5 * w2 + 2] = b;

            u64 d3 = f2fma(P1, NEG1, P0);                 // P0 - P1
            funpack(f2mul(CS2, d3), a, b); sA[16 + 5 * w2 + 3] = a; sB[16 + 5 * w2 + 3] = b;

            u64 s01 = f2add(P0, P1);
            u64 d4 = f2fma(TWO2, P2, f2mul(s01, NEG1));   // 2*P2 - P0 - P1
            funpack(f2mul(C62, d4), a, b); sA[16 + 5 * w2 + 4] = a; sB[16 + 5 * w2 + 4] = b;
        }

        // ---- every 4 w's: coalesced float4 flush of the staged group ----
        if ((w & 3) == 3) {
            __syncthreads();
            const int g = w >> 2;
            const float4* st4 = reinterpret_cast<const float4*>(stage);  // [node][9 f4]
            const long ctaBase = (long)blockIdx.x * NODES_PER_BLOCK;
#pragma unroll 1
            for (int i = t; i < NODES_PER_BLOCK * 9; i += T) {
                int n = i / 9;
                int p = i - n * 9;
                float4 val = st4[i];
                // global col (floats): p==0 -> out0 run; p in 1..3 -> out1 run; p in 4..8 -> out2 run
                int col = (p == 0) ? (4 * g)
                        : (p < 4)  ? (16 + 12 * g + 4 * (p - 1))
                                   : (64 + 20 * g + 4 * (p - 4));
                *reinterpret_cast<float4*>(out + (ctaBase + n) * 144 + col) = val;
            }
            // no trailing sync: next iteration's top __syncthreads() covers reuse
        }
    }
#undef STAGE_SLAB
}

extern "C" void kernel_launch(void* const* d_in, const int* in_sizes, int n_in,
                              void* d_out, int out_size) {
    const float* feats = (const float*)d_in[0];
    const float* msgs  = (const float*)d_in[1];
    const float* w000  = (const float*)d_in[2];
    const float* w101  = (const float*)d_in[3];
    const float* w110  = (const float*)d_in[4];
    const float* w112  = (const float*)d_in[5];
    float* out = (float*)d_out;

    // 8 KB wbuf + 64 KB stash + 36 KB stage = 108 KB per CTA (u64 units: 1024 + 8192 + 4608)
    const int smem_bytes = (1024 + 64 * T + 4608) * (int)sizeof(u64);
    cudaFuncSetAttribute(e3nn_kernel, cudaFuncAttributeMaxDynamicSharedMemorySize, smem_bytes);

    prep_kernel<<<64, 256>>>(w000, w101, w110, w112);
    e3nn_kernel<<<NNODES / NODES_PER_BLOCK, T, smem_bytes>>>(feats, msgs, out);
}

// round 9
// speedup vs baseline: 2.1028x; 1.6028x over previous
#include <cuda_runtime.h>

// E3nnSimpleNodeBlock: out = TensorSquare(feats+msgs), N=131072, MUL=16.
// Round 8: exploit (u,v) symmetry of x (x) x. Symmetric paths (000,110,112) fold to
// triangular u<=v with symmetrized weights (136 instead of 256 terms); 101 path
// refactored as r[u]=W101[u,:]·x0 then outer with x1[u]. ~1.9x fewer FFMA2.
// v fully unrolled -> stage-2 register-direct (no SMEM stash). Keeps R7's
// double-buffered per-w weight slab (cp.async) + staged float4 output flush.

#define T 128
#define NODES_PER_BLOCK 256
#define NNODES 131072

typedef unsigned long long u64;

// Per-w weight slab, splatted f32x2, pre-scaled. u64-indexed layout per w (664 u64):
//   [0,272)    : pairs (q000,q110) per triangular pair tri(v,u) -> ull2 at 2*tri
//   [272,408)  : q112 per triangular pair, u64 at 272+tri
//   [408,664)  : 101 weights W101[u][v] at 408 + u*16 + v
// PW2 = 16 slabs. 16*664*8B = 83 KB.
__device__ __align__(16) u64 PW2[16 * 664];

// ---------- f32x2 helpers ----------
__device__ __forceinline__ u64 f2fma(u64 a, u64 b, u64 c) {
    u64 d;
    asm("fma.rn.f32x2 %0, %1, %2, %3;" : "=l"(d) : "l"(a), "l"(b), "l"(c));
    return d;
}
__device__ __forceinline__ u64 f2add(u64 a, u64 b) {
    u64 d;
    asm("add.rn.f32x2 %0, %1, %2;" : "=l"(d) : "l"(a), "l"(b));
    return d;
}
__device__ __forceinline__ u64 f2mul(u64 a, u64 b) {
    u64 d;
    asm("mul.rn.f32x2 %0, %1, %2;" : "=l"(d) : "l"(a), "l"(b));
    return d;
}
__device__ __forceinline__ u64 fpack(float lo, float hi) {
    u64 d;
    asm("mov.b64 %0, {%1, %2};" : "=l"(d) : "f"(lo), "f"(hi));
    return d;
}
__device__ __forceinline__ void funpack(u64 p, float& lo, float& hi) {
    asm("mov.b64 {%0, %1}, %2;" : "=f"(lo), "=f"(hi) : "l"(p));
}

// ---------- weight prep: symmetrize + scale + splat ----------
__global__ void prep_kernel(const float* __restrict__ w000, const float* __restrict__ w101,
                            const float* __restrict__ w110, const float* __restrict__ w112) {
    int idx = blockIdx.x * blockDim.x + threadIdx.x;   // 0 .. 16*664-1
    if (idx >= 16 * 664) return;
    int w = idx / 664;
    int slot = idx - w * 664;
    const float A000 = 0.04419417382415922f;           // sqrt(1/(2*MUL*MUL))
    const float A110 = 0.02551551815399144f;           // A000/sqrt(3)
    const float A101 = 0.0625f;                        // sqrt(3/MUL^2)/sqrt(3)
    const float A112 = 0.13975424859373686f;           // sqrt(5)/16

    float val;
    if (slot < 408) {
        // triangular regions: pairs region [0,272): entry e=slot/2, comp=slot&1
        // q112 region [272,408): tri = slot-272
        int tri, comp;
        if (slot < 272) { tri = slot >> 1; comp = slot & 1; }
        else            { tri = slot - 272; comp = 2; }
        // invert tri = v*(v+1)/2 + u, u<=v
        int v = 0;
        while ((v + 1) * (v + 2) / 2 <= tri) v++;
        int u = tri - v * (v + 1) / 2;
        int iuv = u * 256 + v * 16 + w;     // W[u][v][w]
        int ivu = v * 256 + u * 16 + w;     // W[v][u][w]
        const float* src = (comp == 0) ? w000 : (comp == 1) ? w110 : w112;
        float A = (comp == 0) ? A000 : (comp == 1) ? A110 : A112;
        val = (u == v) ? A * src[iuv] : A * (src[iuv] + src[ivu]);
    } else {
        int s = slot - 408;
        int u = s >> 4, v = s & 15;
        val = A101 * w101[u * 256 + v * 16 + w];
    }
    reinterpret_cast<float2*>(PW2)[idx] = make_float2(val, val);   // splat
}

// ---------- main kernel ----------
__global__ __launch_bounds__(T, 2) void e3nn_kernel(const float* __restrict__ feats,
                                                    const float* __restrict__ msgs,
                                                    float* __restrict__ out) {
    // SMEM (per CTA, ~47 KB):
    //   wbuf  : u64[2][672]     (10.5 KB)  per-w slab, double-buffered (664 used, 672 pad)
    //   stage : float[256*36]   (36 KB)    4-w-group output staging
    extern __shared__ u64 sm[];
    u64* wbuf = sm;                                           // 2*672 u64
    float* stage = reinterpret_cast<float*>(sm + 1344);       // 9216 floats

    const int t = threadIdx.x;
    const int nA = blockIdx.x * NODES_PER_BLOCK + t;
    const int nB = nA + T;

    // ---- load x = feats + msgs for both nodes, pack into f32x2 registers ----
    u64 px0[16];
    u64 px1[16][3];
    {
        float xA[64], xB[64];
        const float4* fA = reinterpret_cast<const float4*>(feats) + nA * 16;
        const float4* mA = reinterpret_cast<const float4*>(msgs) + nA * 16;
        const float4* fB = reinterpret_cast<const float4*>(feats) + nB * 16;
        const float4* mB = reinterpret_cast<const float4*>(msgs) + nB * 16;
#pragma unroll
        for (int q = 0; q < 16; ++q) {
            float4 f = fA[q], m = mA[q];
            xA[4 * q + 0] = f.x + m.x; xA[4 * q + 1] = f.y + m.y;
            xA[4 * q + 2] = f.z + m.z; xA[4 * q + 3] = f.w + m.w;
        }
#pragma unroll
        for (int q = 0; q < 16; ++q) {
            float4 f = fB[q], m = mB[q];
            xB[4 * q + 0] = f.x + m.x; xB[4 * q + 1] = f.y + m.y;
            xB[4 * q + 2] = f.z + m.z; xB[4 * q + 3] = f.w + m.w;
        }
#pragma unroll
        for (int v = 0; v < 16; ++v) px0[v] = fpack(xA[v], xB[v]);
#pragma unroll
        for (int v = 0; v < 16; ++v) {
#pragma unroll
            for (int i = 0; i < 3; ++i) px1[v][i] = fpack(xA[16 + 3 * v + i], xB[16 + 3 * v + i]);
        }
    }

    // ---- cp.async weight staging: 664 u64 = 332 x 16B chunks per slab ----
#define STAGE_SLAB(wi, buf)                                                               \
    do {                                                                                  \
        const u64* srcb = PW2 + (wi) * 664;                                               \
        u64* dstb = wbuf + (buf) * 672;                                                   \
        unsigned s0 = (unsigned)__cvta_generic_to_shared(dstb + 2 * t);                   \
        asm volatile("cp.async.cg.shared.global [%0], [%1], 16;" ::"r"(s0), "l"(srcb + 2 * t));   \
        asm volatile("cp.async.cg.shared.global [%0], [%1], 16;" ::"r"(s0 + 2048), "l"(srcb + 256 + 2 * t)); \
        if (t < 76) {                                                                     \
            asm volatile("cp.async.cg.shared.global [%0], [%1], 16;" ::"r"(s0 + 4096), "l"(srcb + 512 + 2 * t)); \
        }                                                                                 \
        asm volatile("cp.async.commit_group;");                                           \
    } while (0)

    STAGE_SLAB(0, 0);
    asm volatile("cp.async.wait_group 0;");
    __syncthreads();

    const u64 CS2  = fpack(0.31622776601683794f, 0.31622776601683794f); // 1/sqrt(10)
    const u64 C62  = fpack(0.18257418583505536f, 0.18257418583505536f); // 1/sqrt(30)
    const u64 NEG1 = fpack(-1.0f, -1.0f);
    const u64 TWO2 = fpack(2.0f, 2.0f);

#pragma unroll 1
    for (int w = 0; w < 16; ++w) {
        if (w < 15) STAGE_SLAB(w + 1, (w + 1) & 1);

        const u64* __restrict__ cw = wbuf + (w & 1) * 672;
        const ulonglong2* __restrict__ pairAB = reinterpret_cast<const ulonglong2*>(cw); // [tri]
        const u64* __restrict__ q112w = cw + 272;                                        // [tri]
        const u64* __restrict__ r101w = cw + 408;                                        // [u*16+v]

        u64 acc00 = 0, acc01 = 0;              // out0 paths (000 / 110)
        u64 a10 = 0, a11 = 0, a12 = 0;         // out1 k=0..2
        u64 P0 = 0, P1 = 0, P2 = 0;            // out2 diagonal sums
        u64 Q01 = 0, Q02 = 0, Q12 = 0;         // out2 cross sums

        // ---- symmetric paths: triangular u <= v, v static (full unroll) ----
#pragma unroll
        for (int v = 0; v < 16; ++v) {
            const int tb = v * (v + 1) / 2;
            u64 s000 = 0;
            u64 s110_0 = 0, s110_1 = 0, s110_2 = 0;
            u64 s112_0 = 0, s112_1 = 0, s112_2 = 0;
#pragma unroll
            for (int u = 0; u <= v; ++u) {
                ulonglong2 qab = pairAB[tb + u];    // (q000, q110) broadcast LDS.128
                u64 q2 = q112w[tb + u];             // q112 broadcast LDS.64
                s000   = f2fma(qab.x, px0[u], s000);
                s110_0 = f2fma(qab.y, px1[u][0], s110_0);
                s110_1 = f2fma(qab.y, px1[u][1], s110_1);
                s110_2 = f2fma(qab.y, px1[u][2], s110_2);
                s112_0 = f2fma(q2, px1[u][0], s112_0);
                s112_1 = f2fma(q2, px1[u][1], s112_1);
                s112_2 = f2fma(q2, px1[u][2], s112_2);
            }
            // stage-2: register-direct (v static)
            acc00 = f2fma(s000, px0[v], acc00);
            acc01 = f2fma(s110_0, px1[v][0], acc01);
            acc01 = f2fma(s110_1, px1[v][1], acc01);
            acc01 = f2fma(s110_2, px1[v][2], acc01);

            P0 = f2fma(s112_0, px1[v][0], P0);
            P1 = f2fma(s112_1, px1[v][1], P1);
            P2 = f2fma(s112_2, px1[v][2], P2);
            Q01 = f2fma(s112_0, px1[v][1], Q01);
            Q01 = f2fma(s112_1, px1[v][0], Q01);
            Q02 = f2fma(s112_0, px1[v][2], Q02);
            Q02 = f2fma(s112_2, px1[v][0], Q02);
            Q12 = f2fma(s112_1, px1[v][2], Q12);
            Q12 = f2fma(s112_2, px1[v][1], Q12);
        }

        // ---- 101 path: r[u] = sum_v W101[u,v]*x0[v]; out1 += r[u] * x1[u] ----
#pragma unroll
        for (int u = 0; u < 16; ++u) {
            const ulonglong2* __restrict__ rw =
                reinterpret_cast<const ulonglong2*>(r101w + u * 16);
            u64 r = 0;
#pragma unroll
            for (int g = 0; g < 8; ++g) {
                ulonglong2 q = rw[g];
                r = f2fma(q.x, px0[2 * g + 0], r);
                r = f2fma(q.y, px0[2 * g + 1], r);
            }
            a10 = f2fma(r, px1[u][0], a10);
            a11 = f2fma(r, px1[u][1], a11);
            a12 = f2fma(r, px1[u][2], a12);
        }

        // ---- stage this w's 9 outputs per node into SMEM (group of 4 w's) ----
        {
            const int w2 = w & 3;
            float* sA = stage + t * 36;
            float* sB = stage + (t + T) * 36;
            float a, b;
            funpack(f2add(acc00, acc01), a, b);
            sA[w2] = a; sB[w2] = b;

            funpack(a10, a, b); sA[4 + 3 * w2 + 0] = a; sB[4 + 3 * w2 + 0] = b;
            funpack(a11, a, b); sA[4 + 3 * w2 + 1] = a; sB[4 + 3 * w2 + 1] = b;
            funpack(a12, a, b); sA[4 + 3 * w2 + 2] = a; sB[4 + 3 * w2 + 2] = b;

            funpack(f2mul(CS2, Q01), a, b); sA[16 + 5 * w2 + 0] = a; sB[16 + 5 * w2 + 0] = b;
            funpack(f2mul(CS2, Q02), a, b); sA[16 + 5 * w2 + 1] = a; sB[16 + 5 * w2 + 1] = b;
            funpack(f2mul(CS2, Q12), a, b); sA[16 + 5 * w2 + 2] = a; sB[16 + 5 * w2 + 2] = b;

            u64 d3 = f2fma(P1, NEG1, P0);                 // P0 - P1
            funpack(f2mul(CS2, d3), a, b); sA[16 + 5 * w2 + 3] = a; sB[16 + 5 * w2 + 3] = b;

            u64 s01 = f2add(P0, P1);
            u64 d4 = f2fma(TWO2, P2, f2mul(s01, NEG1));   // 2*P2 - P0 - P1
            funpack(f2mul(C62, d4), a, b); sA[16 + 5 * w2 + 4] = a; sB[16 + 5 * w2 + 4] = b;
        }

        // ---- every 4 w's: coalesced float4 flush of the staged group ----
        if ((w & 3) == 3) {
            __syncthreads();
            const int g = w >> 2;
            const float4* st4 = reinterpret_cast<const float4*>(stage);  // [node][9 f4]
            const long ctaBase = (long)blockIdx.x * NODES_PER_BLOCK;
#pragma unroll 1
            for (int i = t; i < NODES_PER_BLOCK * 9; i += T) {
                int n = i / 9;
                int p = i - n * 9;
                float4 val = st4[i];
                int col = (p == 0) ? (4 * g)
                        : (p < 4)  ? (16 + 12 * g + 4 * (p - 1))
                                   : (64 + 20 * g + 4 * (p - 4));
                *reinterpret_cast<float4*>(out + (ctaBase + n) * 144 + col) = val;
            }
        }

        // prefetched slab done; wbuf/stage safe for next iteration after sync
        asm volatile("cp.async.wait_group 0;");
        __syncthreads();
    }
#undef STAGE_SLAB
}

extern "C" void kernel_launch(void* const* d_in, const int* in_sizes, int n_in,
                              void* d_out, int out_size) {
    const float* feats = (const float*)d_in[0];
    const float* msgs  = (const float*)d_in[1];
    const float* w000  = (const float*)d_in[2];
    const float* w101  = (const float*)d_in[3];
    const float* w110  = (const float*)d_in[4];
    const float* w112  = (const float*)d_in[5];
    float* out = (float*)d_out;

    // 2*672 u64 wbuf + 4608 u64 stage = 5952 u64 = 47.6 KB
    const int smem_bytes = (1344 + 4608) * (int)sizeof(u64);
    cudaFuncSetAttribute(e3nn_kernel, cudaFuncAttributeMaxDynamicSharedMemorySize, smem_bytes);

    prep_kernel<<<(16 * 664 + 255) / 256, 256>>>(w000, w101, w110, w112);
    e3nn_kernel<<<NNODES / NODES_PER_BLOCK, T, smem_bytes>>>(feats, msgs, out);
}